// round 9
// baseline (speedup 1.0000x reference)
#include <cuda_runtime.h>
#include <math.h>

// Problem constants
#define Sx   128
#define Bx   32
#define Dx   512
#define Hx   512
#define G4x  2048   // 4*H
#define Vx   8000
#define SBx  4096   // S*B
#define NKC  16     // k-chunks for hidden GEMM (512/32)

// ---------------------------------------------------------------------------
// Device scratch (static globals: allocation-free, allowed by harness rules)
// ---------------------------------------------------------------------------
__device__ float g_gates[2][(size_t)Sx * Bx * G4x];   // per-dir gate pre-activations (layer-reused), 67 MB
__device__ float g_h0[2][(size_t)Sx * Bx * Hx];       // layer-0 hidden states (actual time order)
__device__ float g_h1[2][(size_t)Sx * Bx * Hx];       // layer-1 hidden states
__device__ float g_c[2][Bx * Hx];                     // cell state (layer-reused)
__device__ float g_part[2][NKC][Bx * G4x];            // k-split partials of hidden GEMM (8 MB)

// ---------------------------------------------------------------------------
// Generic fp32 GEMM:  O[M,N] = A[M,K] * W[N,K]^T + b1[n] (+ b2[n])
// BM=128, BN=128, BK=16, 256 threads, 8x8 register tile.
// a_sel: 0 -> Aext, 1 -> g_h0, 2 -> g_h1   (plus a_off elements)
// o_sel: 0 -> Oext, 1 -> g_gates           (plus o_off elements)
// M must be a multiple of 128; K a multiple of 16; N bounds-checked (mult of 4).
// ---------------------------------------------------------------------------
__global__ __launch_bounds__(256) void gemm_bias(
    const float* __restrict__ Aext, int a_sel, long long a_off,
    const float* __restrict__ W,
    const float* __restrict__ b1, const float* __restrict__ b2,
    float* __restrict__ Oext, int o_sel, long long o_off,
    int M, int N, int K)
{
    __shared__ float As[16 * 128];
    __shared__ float Ws[16 * 128];

    const float* A = (a_sel == 0) ? Aext : ((a_sel == 1) ? &g_h0[0][0] : &g_h1[0][0]);
    A += a_off;
    float* O = (o_sel == 0) ? Oext : &g_gates[0][0];
    O += o_off;

    const int tid  = threadIdx.x;
    const int n0   = blockIdx.x * 128;
    const int m0   = blockIdx.y * 128;
    const int lr   = tid & 127;          // row within tile for loads
    const int lk   = (tid >> 7) * 8;     // k-offset (0 or 8) for loads
    const int trow = tid >> 4;           // 0..15 -> 8 m-rows each
    const int tcol = tid & 15;           // 0..15 -> n-cols {tcol*4..+3} U {64+tcol*4..+3}

    float acc[8][8];
#pragma unroll
    for (int i = 0; i < 8; i++)
#pragma unroll
        for (int j = 0; j < 8; j++) acc[i][j] = 0.f;

    for (int k0 = 0; k0 < K; k0 += 16) {
        // global loads (coalesced within 8-float row segments)
        const float* ap = A + (size_t)(m0 + lr) * K + k0 + lk;
        float4 a0 = *(const float4*)(ap);
        float4 a1 = *(const float4*)(ap + 4);
        float4 w0 = make_float4(0.f, 0.f, 0.f, 0.f), w1 = w0;
        if (n0 + lr < N) {
            const float* wp = W + (size_t)(n0 + lr) * K + k0 + lk;
            w0 = *(const float4*)(wp);
            w1 = *(const float4*)(wp + 4);
        }
        __syncthreads();   // protect previous iteration's reads
        As[(lk + 0) * 128 + lr] = a0.x;  As[(lk + 1) * 128 + lr] = a0.y;
        As[(lk + 2) * 128 + lr] = a0.z;  As[(lk + 3) * 128 + lr] = a0.w;
        As[(lk + 4) * 128 + lr] = a1.x;  As[(lk + 5) * 128 + lr] = a1.y;
        As[(lk + 6) * 128 + lr] = a1.z;  As[(lk + 7) * 128 + lr] = a1.w;
        Ws[(lk + 0) * 128 + lr] = w0.x;  Ws[(lk + 1) * 128 + lr] = w0.y;
        Ws[(lk + 2) * 128 + lr] = w0.z;  Ws[(lk + 3) * 128 + lr] = w0.w;
        Ws[(lk + 4) * 128 + lr] = w1.x;  Ws[(lk + 5) * 128 + lr] = w1.y;
        Ws[(lk + 6) * 128 + lr] = w1.z;  Ws[(lk + 7) * 128 + lr] = w1.w;
        __syncthreads();

#pragma unroll
        for (int k = 0; k < 16; k++) {
            float4 av0 = *(const float4*)&As[k * 128 + trow * 8];
            float4 av1 = *(const float4*)&As[k * 128 + trow * 8 + 4];
            float4 wv0 = *(const float4*)&Ws[k * 128 + tcol * 4];
            float4 wv1 = *(const float4*)&Ws[k * 128 + 64 + tcol * 4];
            float av[8] = {av0.x, av0.y, av0.z, av0.w, av1.x, av1.y, av1.z, av1.w};
            float wv[8] = {wv0.x, wv0.y, wv0.z, wv0.w, wv1.x, wv1.y, wv1.z, wv1.w};
#pragma unroll
            for (int i = 0; i < 8; i++)
#pragma unroll
                for (int j = 0; j < 8; j++) acc[i][j] += av[i] * wv[j];
        }
    }

    // epilogue with bias
    const int nA = n0 + tcol * 4;
    const int nB = n0 + 64 + tcol * 4;
    float4 bA = make_float4(0.f, 0.f, 0.f, 0.f), bB = bA;
    if (nA < N) {
        bA = *(const float4*)(b1 + nA);
        if (b2) { float4 t = *(const float4*)(b2 + nA); bA.x += t.x; bA.y += t.y; bA.z += t.z; bA.w += t.w; }
    }
    if (nB < N) {
        bB = *(const float4*)(b1 + nB);
        if (b2) { float4 t = *(const float4*)(b2 + nB); bB.x += t.x; bB.y += t.y; bB.z += t.z; bB.w += t.w; }
    }
#pragma unroll
    for (int i = 0; i < 8; i++) {
        size_t m = (size_t)(m0 + trow * 8 + i);
        if (nA < N) {
            float4 r = make_float4(acc[i][0] + bA.x, acc[i][1] + bA.y,
                                   acc[i][2] + bA.z, acc[i][3] + bA.w);
            *(float4*)(O + m * N + nA) = r;
        }
        if (nB < N) {
            float4 r = make_float4(acc[i][4] + bB.x, acc[i][5] + bB.y,
                                   acc[i][6] + bB.z, acc[i][7] + bB.w);
            *(float4*)(O + m * N + nB) = r;
        }
    }
}

// ---------------------------------------------------------------------------
// LSTM hidden GEMM (one time step, both directions), k-split:
//   g_part[dir][kc][b][n] = sum_{k in chunk kc} h_prev[b][k] * Whh[n][k]
// grid (8 n-tiles of 256, 16 k-chunks of 32, 2 dirs), 256 threads.
// Thread tile: 4 batch x 8 gate-cols (cols split as {tx*4} U {128+tx*4}).
// ---------------------------------------------------------------------------
__global__ __launch_bounds__(256) void lstm_hidden(
    const float* __restrict__ Whf, const float* __restrict__ Whb,
    int layer_sel, int t, int first)
{
    __shared__ float hs[32 * 32];    // [k][b]
    __shared__ float ws[32 * 256];   // [k][n]

    const int dir = blockIdx.z;
    const int tt  = dir ? (Sx - 1 - t) : t;                 // actual time processed
    int tp        = dir ? (tt + 1) : (t - 1);               // previous actual time
    if (first) tp = tt;                                     // clamp (value unused)
    const float* W = dir ? Whb : Whf;
    const float* hbase = layer_sel ? &g_h1[0][0] : &g_h0[0][0];
    const float* hp = hbase + ((size_t)dir * Sx + tp) * (Bx * Hx);

    const int n0  = blockIdx.x * 256;
    const int k0  = blockIdx.y * 32;
    const int tid = threadIdx.x;

    // load W tile: one row (32 k's) per thread, conflict-free transposed STS
    {
        const float4* wr = (const float4*)(W + (size_t)(n0 + tid) * Hx + k0);
#pragma unroll
        for (int i = 0; i < 8; i++) {
            float4 v = wr[i];
            ws[(i * 4 + 0) * 256 + tid] = v.x;
            ws[(i * 4 + 1) * 256 + tid] = v.y;
            ws[(i * 4 + 2) * 256 + tid] = v.z;
            ws[(i * 4 + 3) * 256 + tid] = v.w;
        }
    }
    // load h tile (zeros at first step)
    {
        const int b = tid & 31, kb = (tid >> 5) * 4;
        float4 v = make_float4(0.f, 0.f, 0.f, 0.f);
        if (!first) v = *(const float4*)(hp + (size_t)b * Hx + k0 + kb);
        hs[(kb + 0) * 32 + b] = v.x;  hs[(kb + 1) * 32 + b] = v.y;
        hs[(kb + 2) * 32 + b] = v.z;  hs[(kb + 3) * 32 + b] = v.w;
    }
    __syncthreads();

    const int tx = tid & 31;   // n-group
    const int ty = tid >> 5;   // b-group (0..7)
    float acc[4][8];
#pragma unroll
    for (int i = 0; i < 4; i++)
#pragma unroll
        for (int j = 0; j < 8; j++) acc[i][j] = 0.f;

#pragma unroll
    for (int k = 0; k < 32; k++) {
        float4 hv = *(const float4*)&hs[k * 32 + ty * 4];
        float4 w0 = *(const float4*)&ws[k * 256 + tx * 4];
        float4 w1 = *(const float4*)&ws[k * 256 + 128 + tx * 4];
        float hvv[4] = {hv.x, hv.y, hv.z, hv.w};
        float wvv[8] = {w0.x, w0.y, w0.z, w0.w, w1.x, w1.y, w1.z, w1.w};
#pragma unroll
        for (int i = 0; i < 4; i++)
#pragma unroll
            for (int j = 0; j < 8; j++) acc[i][j] += hvv[i] * wvv[j];
    }

    float* P = &g_part[dir][blockIdx.y][0];
#pragma unroll
    for (int i = 0; i < 4; i++) {
        const int b = ty * 4 + i;
        *(float4*)&P[(size_t)b * G4x + n0 + tx * 4] =
            make_float4(acc[i][0], acc[i][1], acc[i][2], acc[i][3]);
        *(float4*)&P[(size_t)b * G4x + n0 + 128 + tx * 4] =
            make_float4(acc[i][4], acc[i][5], acc[i][6], acc[i][7]);
    }
}

// ---------------------------------------------------------------------------
// LSTM cell update: sum input gates + k-split partials, apply activations,
// update c, write h_all[tt]. grid (64, 2 dirs), 256 threads; idx = b*H + j.
// ---------------------------------------------------------------------------
__global__ __launch_bounds__(256) void lstm_act(int layer_sel, int t, int first)
{
    const int dir = blockIdx.y;
    const int tt  = dir ? (Sx - 1 - t) : t;
    const int idx = blockIdx.x * 256 + threadIdx.x;   // 0..16383
    const int b   = idx >> 9;
    const int j   = idx & 511;

    const float* g = &g_gates[dir][((size_t)tt * Bx + b) * G4x];
    float gi = g[j];
    float gf = g[j + Hx];
    float gg = g[j + 2 * Hx];
    float go = g[j + 3 * Hx];
#pragma unroll
    for (int kc = 0; kc < NKC; kc++) {
        const float* p = &g_part[dir][kc][(size_t)b * G4x];
        gi += p[j];
        gf += p[j + Hx];
        gg += p[j + 2 * Hx];
        go += p[j + 3 * Hx];
    }

    const float cold = first ? 0.f : g_c[dir][idx];
    const float is = 1.f / (1.f + expf(-gi));
    const float fs = 1.f / (1.f + expf(-gf));
    const float os = 1.f / (1.f + expf(-go));
    const float gt = tanhf(gg);
    const float cn = fs * cold + is * gt;
    const float hn = os * tanhf(cn);

    g_c[dir][idx] = cn;
    float* hb = layer_sel ? &g_h1[0][0] : &g_h0[0][0];
    hb[((size_t)dir * Sx + tt) * (Bx * Hx) + idx] = hn;
}

// ---------------------------------------------------------------------------
// Host orchestration (graph-capturable: kernel launches only)
// ---------------------------------------------------------------------------
extern "C" void kernel_launch(void* const* d_in, const int* in_sizes, int n_in,
                              void* d_out, int out_size)
{
    (void)in_sizes; (void)n_in; (void)out_size;
    const float* x     = (const float*)d_in[0];
    const float* Wf_ih = (const float*)d_in[1];
    const float* Wf_hh = (const float*)d_in[2];
    const float* bf_ih = (const float*)d_in[3];
    const float* bf_hh = (const float*)d_in[4];
    const float* Wb_ih = (const float*)d_in[5];
    const float* Wb_hh = (const float*)d_in[6];
    const float* bb_ih = (const float*)d_in[7];
    const float* bb_hh = (const float*)d_in[8];
    const float* W_fwd = (const float*)d_in[9];
    const float* b_fwd = (const float*)d_in[10];
    const float* W_bwd = (const float*)d_in[11];
    const float* b_bwd = (const float*)d_in[12];
    float* out = (float*)d_out;

    const dim3 gridL(16, 32);          // N=2048, M=4096
    const dim3 gridP(63, 32);          // N=8000 (ceil), M=4096
    const dim3 gridH(8, NKC, 2);       // hidden GEMM
    const dim3 gridA(64, 2);           // activations
    const long long DIRG = (long long)Sx * Bx * G4x;   // per-dir gates stride
    const long long DIRH = (long long)Sx * Bx * Hx;    // per-dir h stride
    const long long WL1  = (long long)G4x * Hx;        // layer-1 weight offset

    // ---- Layer 0: input projections (biases folded in) ----
    gemm_bias<<<gridL, 256>>>(x, 0, 0, Wf_ih, bf_ih, bf_hh, nullptr, 1, 0,    SBx, G4x, Dx);
    gemm_bias<<<gridL, 256>>>(x, 0, 0, Wb_ih, bb_ih, bb_hh, nullptr, 1, DIRG, SBx, G4x, Dx);

    // ---- Layer 0: recurrence ----
    for (int t = 0; t < Sx; t++) {
        lstm_hidden<<<gridH, 256>>>(Wf_hh, Wb_hh, 0, t, t == 0);
        lstm_act<<<gridA, 256>>>(0, t, t == 0);
    }

    // ---- Layer 1: input projections from layer-0 h ----
    gemm_bias<<<gridL, 256>>>(nullptr, 1, 0,    Wf_ih + WL1, bf_ih + G4x, bf_hh + G4x, nullptr, 1, 0,    SBx, G4x, Hx);
    gemm_bias<<<gridL, 256>>>(nullptr, 1, DIRH, Wb_ih + WL1, bb_ih + G4x, bb_hh + G4x, nullptr, 1, DIRG, SBx, G4x, Hx);

    // ---- Layer 1: recurrence ----
    for (int t = 0; t < Sx; t++) {
        lstm_hidden<<<gridH, 256>>>(Wf_hh + WL1, Wb_hh + WL1, 1, t, t == 0);
        lstm_act<<<gridA, 256>>>(1, t, t == 0);
    }

    // ---- Output projections (fully overwrite d_out) ----
    gemm_bias<<<gridP, 256>>>(nullptr, 2, 0,    W_fwd, b_fwd, nullptr, out, 0, 0,                    SBx, Vx, Hx);
    gemm_bias<<<gridP, 256>>>(nullptr, 2, DIRH, W_bwd, b_bwd, nullptr, out, 0, (long long)SBx * Vx, SBx, Vx, Hx);
}